// round 9
// baseline (speedup 1.0000x reference)
#include <cuda_runtime.h>
#include <cuda_bf16.h>
#include <cuda_fp16.h>
#include <cstdint>

typedef unsigned long long ull;
typedef unsigned int uint;

#define MAXN 100000
#define MAXE 3200000
#define D 256
#define SBLK 1024
#define MAXPART 128

// ---------------- scratch ----------------
__device__ float  g_side[(size_t)MAXN * D];
__device__ __half g_half[(size_t)MAXN * D];
__device__ ull    g_epack[MAXE];
__device__ int    g_hist[MAXN];
__device__ int    g_off[MAXN + 1];
__device__ int    g_cur[MAXN];
__device__ int    g_part[MAXPART];

__device__ __forceinline__ float lrelu(float x) { return x > 0.0f ? x : 0.01f * x; }
__device__ __forceinline__ uint h2u(__half2 h) { return *reinterpret_cast<uint*>(&h); }
__device__ __forceinline__ __half2 u2h(uint u) { return *reinterpret_cast<__half2*>(&u); }

// m16n8k16 fp16 mma, fp32 accum: D += A*B
__device__ __forceinline__ void mma16(float* d, const uint* a, const uint* b) {
    asm volatile(
        "mma.sync.aligned.m16n8k16.row.col.f32.f16.f16.f32 "
        "{%0,%1,%2,%3}, {%4,%5,%6,%7}, {%8,%9}, {%0,%1,%2,%3};"
        : "+f"(d[0]), "+f"(d[1]), "+f"(d[2]), "+f"(d[3])
        : "r"(a[0]), "r"(a[1]), "r"(a[2]), "r"(a[3]), "r"(b[0]), "r"(b[1]));
}

// ---------------- 0. fp32 -> fp16 gather table ----------------
__global__ void convert_kernel(const float4* __restrict__ ego4, int n4) {
    int i = blockIdx.x * blockDim.x + threadIdx.x;
    if (i < n4) {
        float4 v = ego4[i];
        uint2 o;
        o.x = h2u(__floats2half2_rn(v.x, v.y));
        o.y = h2u(__floats2half2_rn(v.z, v.w));
        ((uint2*)g_half)[i] = o;
    }
}

// ---------------- 1. zero histogram ----------------
__global__ void zero_hist_kernel(int n) {
    int i = blockIdx.x * blockDim.x + threadIdx.x;
    if (i < n) g_hist[i] = 0;
}

// ---------------- 2. histogram of edge rows ----------------
__global__ void hist_kernel(const int* __restrict__ rows, int e) {
    int i = blockIdx.x * blockDim.x + threadIdx.x;
    if (i < e) atomicAdd(&g_hist[rows[i]], 1);
}

// ---------------- 3a. per-block reduce of hist ----------------
__global__ __launch_bounds__(SBLK) void scan_reduce_kernel(int n) {
    __shared__ int ws[32];
    int tid = threadIdx.x, lane = tid & 31, w = tid >> 5;
    int i = blockIdx.x * SBLK + tid;
    int x = (i < n) ? g_hist[i] : 0;
    #pragma unroll
    for (int d = 16; d; d >>= 1) x += __shfl_down_sync(0xffffffffu, x, d);
    if (lane == 0) ws[w] = x;
    __syncthreads();
    if (w == 0) {
        int s = ws[lane];
        #pragma unroll
        for (int d = 16; d; d >>= 1) s += __shfl_down_sync(0xffffffffu, s, d);
        if (lane == 0) g_part[blockIdx.x] = s;
    }
}

// ---------------- 3b. exclusive scan of partials ----------------
__global__ void scan_part_kernel(int nb) {
    __shared__ int wsum[4];
    int t = threadIdx.x, lane = t & 31, w = t >> 5;
    int v = (t < nb) ? g_part[t] : 0;
    int x = v;
    #pragma unroll
    for (int d = 1; d < 32; d <<= 1) {
        int y = __shfl_up_sync(0xffffffffu, x, d);
        if (lane >= d) x += y;
    }
    if (lane == 31) wsum[w] = x;
    __syncthreads();
    if (t == 0) {
        int a = 0;
        #pragma unroll
        for (int k = 0; k < 4; k++) { int b = wsum[k]; wsum[k] = a; a += b; }
    }
    __syncthreads();
    if (t < nb) g_part[t] = x + wsum[w] - v;
    if (t == 0) g_off[0] = 0;
}

// ---------------- 3c. final block scans with base offset ----------------
__global__ __launch_bounds__(SBLK) void scan_final_kernel(int n) {
    __shared__ int ws[32];
    int tid = threadIdx.x, lane = tid & 31, w = tid >> 5;
    int i = blockIdx.x * SBLK + tid;
    int v = (i < n) ? g_hist[i] : 0;
    int x = v;
    #pragma unroll
    for (int d = 1; d < 32; d <<= 1) {
        int y = __shfl_up_sync(0xffffffffu, x, d);
        if (lane >= d) x += y;
    }
    if (lane == 31) ws[w] = x;
    __syncthreads();
    if (w == 0) {
        int s = ws[lane];
        #pragma unroll
        for (int d = 1; d < 32; d <<= 1) {
            int y = __shfl_up_sync(0xffffffffu, s, d);
            if (lane >= d) s += y;
        }
        ws[lane] = s;
    }
    __syncthreads();
    int incl = x + g_part[blockIdx.x] + (w > 0 ? ws[w - 1] : 0);
    if (i < n) {
        g_off[i + 1] = incl;
        g_cur[i]     = incl - v;
    }
}

// ---------------- 4. scatter edges (packed 8B records) ----------------
__global__ void scatter_kernel(const int* __restrict__ rows, const int* __restrict__ cols,
                               const float* __restrict__ vals, int e) {
    int i = blockIdx.x * blockDim.x + threadIdx.x;
    if (i < e) {
        int r = rows[i];
        ull rec = (ull)(uint)cols[i] | ((ull)__float_as_uint(vals[i]) << 32);
        int p = atomicAdd(&g_cur[r], 1);
        g_epack[p] = rec;
    }
}

// ---------------- 5. CSR SpMM over fp16 table ----------------
__global__ __launch_bounds__(64) void spmm_kernel() {
    int node = blockIdx.x;
    int t = threadIdx.x;
    const uint2* tab = (const uint2*)g_half;
    int beg = g_off[node], end = g_off[node + 1];
    float4 a0 = {0,0,0,0}, a1 = a0, a2 = a0, a3 = a0;
    int e = beg;
    for (; e + 4 <= end; e += 4) {
        ull r0 = g_epack[e],   r1 = g_epack[e+1];
        ull r2 = g_epack[e+2], r3 = g_epack[e+3];
        uint  c0 = (uint)r0, c1 = (uint)r1, c2 = (uint)r2, c3 = (uint)r3;
        float v0 = __uint_as_float((uint)(r0 >> 32));
        float v1 = __uint_as_float((uint)(r1 >> 32));
        float v2 = __uint_as_float((uint)(r2 >> 32));
        float v3 = __uint_as_float((uint)(r3 >> 32));
        uint2 x0 = tab[(size_t)c0 * 64 + t];
        uint2 x1 = tab[(size_t)c1 * 64 + t];
        uint2 x2 = tab[(size_t)c2 * 64 + t];
        uint2 x3 = tab[(size_t)c3 * 64 + t];
        float2 p, q;
        p = __half22float2(u2h(x0.x)); q = __half22float2(u2h(x0.y));
        a0.x += v0*p.x; a0.y += v0*p.y; a0.z += v0*q.x; a0.w += v0*q.y;
        p = __half22float2(u2h(x1.x)); q = __half22float2(u2h(x1.y));
        a1.x += v1*p.x; a1.y += v1*p.y; a1.z += v1*q.x; a1.w += v1*q.y;
        p = __half22float2(u2h(x2.x)); q = __half22float2(u2h(x2.y));
        a2.x += v2*p.x; a2.y += v2*p.y; a2.z += v2*q.x; a2.w += v2*q.y;
        p = __half22float2(u2h(x3.x)); q = __half22float2(u2h(x3.y));
        a3.x += v3*p.x; a3.y += v3*p.y; a3.z += v3*q.x; a3.w += v3*q.y;
    }
    for (; e < end; e++) {
        ull r0 = g_epack[e];
        uint c = (uint)r0;
        float v = __uint_as_float((uint)(r0 >> 32));
        uint2 x = tab[(size_t)c * 64 + t];
        float2 p = __half22float2(u2h(x.x));
        float2 q = __half22float2(u2h(x.y));
        a0.x += v*p.x; a0.y += v*p.y; a0.z += v*q.x; a0.w += v*q.y;
    }
    float4 r;
    r.x = (a0.x + a1.x) + (a2.x + a3.x);
    r.y = (a0.y + a1.y) + (a2.y + a3.y);
    r.z = (a0.z + a1.z) + (a2.z + a3.z);
    r.w = (a0.w + a1.w) + (a2.w + a3.w);
    ((float4*)g_side)[(size_t)node * 64 + t] = r;
}

// ---------------- 6. fused dual GEMM via fp16 m16n8k16 tensor cores -------
// Block tile 128x128, BK=32 (2 k16 steps), 8 warps (2m x 4n), warp 64x32.
// Smem tiles: half [128 rows][40 halves] = stride 20 uints.
//   Fragment LDS banks: (20*g + c) mod 32, bijective over g<8,c<4 -> conflict-free.
#define TBM 128
#define TBN 128
#define TBK 32
#define HSTR 20                 // uints per row (32 halves + 8 pad)
#define TILE_U (TBM * HSTR)     // 2560 uints per tile

__global__ __launch_bounds__(256, 1) void gemm_mma_kernel(
    const float* __restrict__ ego,
    const float* __restrict__ W1, const float* __restrict__ b1,
    const float* __restrict__ W2, const float* __restrict__ b2,
    float* __restrict__ out, int n)
{
    __shared__ uint smem[4 * TILE_U];    // 40KB
    uint* Xs  = smem;                    // (ego+side) fp16
    uint* Xp  = Xs + TILE_U;             // (ego*side) fp16
    uint* W1t = Xp + TILE_U;
    uint* W2t = W1t + TILE_U;

    const int tid  = threadIdx.x;
    const int lane = tid & 31;
    const int wid  = tid >> 5;
    const int wm   = (wid >> 2) * 64;
    const int wn   = (wid & 3) * 32;
    const int g    = lane >> 2;
    const int c    = lane & 3;

    const int node0 = blockIdx.x * TBM;
    const int jbase = blockIdx.y * TBN;

    const int pm   = tid >> 1;
    const int ph   = tid & 1;

    float acc1[4][4][4];
    float acc2[4][4][4];
    #pragma unroll
    for (int i = 0; i < 4; i++)
        #pragma unroll
        for (int j = 0; j < 4; j++)
            #pragma unroll
            for (int r = 0; r < 4; r++) { acc1[i][j][r] = 0.f; acc2[i][j][r] = 0.f; }

    int xrow = node0 + pm; if (xrow >= n) xrow = n - 1;
    const float4* egoR  = (const float4*)(ego    + (size_t)xrow * D);
    const float4* sideR = (const float4*)(g_side + (size_t)xrow * D);
    const float4* w1R   = (const float4*)(W1 + (size_t)(jbase + pm) * D);
    const float4* w2R   = (const float4*)(W2 + (size_t)(jbase + pm) * D);

    for (int ck = 0; ck < D / TBK; ck++) {
        const int kq0 = ck * (TBK / 4);          // float4 index base
        __syncthreads();
        // ---- produce X tiles (fp16) ----
        #pragma unroll
        for (int q = 0; q < 4; q++) {
            int f = ph * 4 + q;                  // float4 index within row (0..7)
            float4 e4 = egoR[kq0 + f];
            float4 s4 = sideR[kq0 + f];
            uint2 sv, pv;
            sv.x = h2u(__floats2half2_rn(e4.x + s4.x, e4.y + s4.y));
            sv.y = h2u(__floats2half2_rn(e4.z + s4.z, e4.w + s4.w));
            pv.x = h2u(__floats2half2_rn(e4.x * s4.x, e4.y * s4.y));
            pv.y = h2u(__floats2half2_rn(e4.z * s4.z, e4.w * s4.w));
            *(uint2*)(Xs + pm * HSTR + f * 2) = sv;
            *(uint2*)(Xp + pm * HSTR + f * 2) = pv;
        }
        // ---- produce W tiles (fp16) ----
        #pragma unroll
        for (int q = 0; q < 4; q++) {
            int f = ph * 4 + q;
            float4 w1v = w1R[kq0 + f];
            float4 w2v = w2R[kq0 + f];
            uint2 a, b;
            a.x = h2u(__floats2half2_rn(w1v.x, w1v.y));
            a.y = h2u(__floats2half2_rn(w1v.z, w1v.w));
            b.x = h2u(__floats2half2_rn(w2v.x, w2v.y));
            b.y = h2u(__floats2half2_rn(w2v.z, w2v.w));
            *(uint2*)(W1t + pm * HSTR + f * 2) = a;
            *(uint2*)(W2t + pm * HSTR + f * 2) = b;
        }
        __syncthreads();
        // ---- consume: 2 k16-steps ----
        #pragma unroll
        for (int s = 0; s < 2; s++) {
            const int so = s * 8;                // uint offset of k16 group
            uint aS[4][4], aP[4][4];
            #pragma unroll
            for (int am = 0; am < 4; am++) {
                int base = (wm + am * 16 + g) * HSTR + so + c;
                aS[am][0] = Xs[base];
                aS[am][1] = Xs[base + 8 * HSTR];
                aS[am][2] = Xs[base + 4];
                aS[am][3] = Xs[base + 8 * HSTR + 4];
                aP[am][0] = Xp[base];
                aP[am][1] = Xp[base + 8 * HSTR];
                aP[am][2] = Xp[base + 4];
                aP[am][3] = Xp[base + 8 * HSTR + 4];
            }
            uint bW1[4][2], bW2[4][2];
            #pragma unroll
            for (int bn = 0; bn < 4; bn++) {
                int base = (wn + bn * 8 + g) * HSTR + so + c;
                bW1[bn][0] = W1t[base];
                bW1[bn][1] = W1t[base + 4];
                bW2[bn][0] = W2t[base];
                bW2[bn][1] = W2t[base + 4];
            }
            #pragma unroll
            for (int am = 0; am < 4; am++)
                #pragma unroll
                for (int bn = 0; bn < 4; bn++) {
                    mma16(acc1[am][bn], aS[am], bW1[bn]);
                    mma16(acc2[am][bn], aP[am], bW2[bn]);
                }
        }
    }

    // ---- epilogue: bias + leaky_relu + add ----
    #pragma unroll
    for (int bn = 0; bn < 4; bn++) {
        int col = jbase + wn + bn * 8 + c * 2;
        float2 bb1 = *(const float2*)(b1 + col);
        float2 bb2 = *(const float2*)(b2 + col);
        #pragma unroll
        for (int am = 0; am < 4; am++) {
            int r0 = node0 + wm + am * 16 + g;
            int r1 = r0 + 8;
            if (r0 < n) {
                float2 o;
                o.x = lrelu(acc1[am][bn][0] + bb1.x) + lrelu(acc2[am][bn][0] + bb2.x);
                o.y = lrelu(acc1[am][bn][1] + bb1.y) + lrelu(acc2[am][bn][1] + bb2.y);
                *(float2*)(out + (size_t)r0 * D + col) = o;
            }
            if (r1 < n) {
                float2 o;
                o.x = lrelu(acc1[am][bn][2] + bb1.x) + lrelu(acc2[am][bn][2] + bb2.x);
                o.y = lrelu(acc1[am][bn][3] + bb1.y) + lrelu(acc2[am][bn][3] + bb2.y);
                *(float2*)(out + (size_t)r1 * D + col) = o;
            }
        }
    }
}

// ---------------- launch ----------------
extern "C" void kernel_launch(void* const* d_in, const int* in_sizes, int n_in,
                              void* d_out, int out_size) {
    const float* ego   = (const float*)d_in[0];
    const float* evals = (const float*)d_in[1];
    const float* W1    = (const float*)d_in[2];
    const float* b1    = (const float*)d_in[3];
    const float* W2    = (const float*)d_in[4];
    const float* b2    = (const float*)d_in[5];
    const int*   erows = (const int*)d_in[6];
    const int*   ecols = (const int*)d_in[7];
    float* out = (float*)d_out;

    int N = in_sizes[0] / D;
    int E = in_sizes[1];
    if (N > MAXN) N = MAXN;
    if (E > MAXE) E = MAXE;

    int n4 = N * (D / 4);
    int nscan = (N + SBLK - 1) / SBLK;
    convert_kernel<<<(n4 + 255) / 256, 256>>>((const float4*)ego, n4);
    zero_hist_kernel<<<(N + 255) / 256, 256>>>(N);
    hist_kernel<<<(E + 255) / 256, 256>>>(erows, E);
    scan_reduce_kernel<<<nscan, SBLK>>>(N);
    scan_part_kernel<<<1, 128>>>(nscan);
    scan_final_kernel<<<nscan, SBLK>>>(N);
    scatter_kernel<<<(E + 255) / 256, 256>>>(erows, ecols, evals, E);
    spmm_kernel<<<N, 64>>>();
    dim3 ggrid((N + TBM - 1) / TBM, D / TBN);
    gemm_mma_kernel<<<ggrid, 256>>>(ego, W1, b1, W2, b2, out, N);
}

// round 10
// speedup vs baseline: 1.2779x; 1.2779x over previous
#include <cuda_runtime.h>
#include <cuda_bf16.h>
#include <cuda_fp16.h>
#include <cstdint>

typedef unsigned long long ull;
typedef unsigned int uint;

#define MAXN 100000
#define MAXE 3200000
#define D 256
#define SBLK 1024
#define MAXPART 128

// ---------------- scratch ----------------
__device__ float  g_side[(size_t)MAXN * D];
__device__ __half g_half[(size_t)MAXN * D];
__device__ ull    g_epack[MAXE];
__device__ int    g_hist[MAXN];
__device__ int    g_off[MAXN + 1];
__device__ int    g_cur[MAXN];
__device__ int    g_part[MAXPART];

__device__ __forceinline__ float lrelu(float x) { return x > 0.0f ? x : 0.01f * x; }
__device__ __forceinline__ uint f2tf32(float f) {
    uint u; asm("cvt.rna.tf32.f32 %0, %1;" : "=r"(u) : "f"(f)); return u;
}
__device__ __forceinline__ uint h2u(__half2 h) { return *reinterpret_cast<uint*>(&h); }
__device__ __forceinline__ __half2 u2h(uint u) { return *reinterpret_cast<__half2*>(&u); }

// m16n8k8 tf32 mma, D += A*B  (fastest legacy-mma path on sm_103a; fp16 k16 is 2x slower)
__device__ __forceinline__ void mma8(float* d, const uint* a, const uint* b) {
    asm volatile(
        "mma.sync.aligned.m16n8k8.row.col.f32.tf32.tf32.f32 "
        "{%0,%1,%2,%3}, {%4,%5,%6,%7}, {%8,%9}, {%0,%1,%2,%3};"
        : "+f"(d[0]), "+f"(d[1]), "+f"(d[2]), "+f"(d[3])
        : "r"(a[0]), "r"(a[1]), "r"(a[2]), "r"(a[3]), "r"(b[0]), "r"(b[1]));
}

// ---------------- 0. fused: zero hist + fp32->fp16 gather table ----------
__global__ void prep_kernel(const float4* __restrict__ ego4, int n4, int n, int zb) {
    if ((int)blockIdx.x < zb) {
        int i = blockIdx.x * 256 + threadIdx.x;
        if (i < n) g_hist[i] = 0;
    } else {
        int i = (blockIdx.x - zb) * 256 + threadIdx.x;
        if (i < n4) {
            float4 v = ego4[i];
            uint2 o;
            o.x = h2u(__floats2half2_rn(v.x, v.y));
            o.y = h2u(__floats2half2_rn(v.z, v.w));
            ((uint2*)g_half)[i] = o;
        }
    }
}

// ---------------- 2. histogram of edge rows ----------------
__global__ void hist_kernel(const int* __restrict__ rows, int e) {
    int i = blockIdx.x * blockDim.x + threadIdx.x;
    if (i < e) atomicAdd(&g_hist[rows[i]], 1);
}

// ---------------- 3a. per-block reduce of hist ----------------
__global__ __launch_bounds__(SBLK) void scan_reduce_kernel(int n) {
    __shared__ int ws[32];
    int tid = threadIdx.x, lane = tid & 31, w = tid >> 5;
    int i = blockIdx.x * SBLK + tid;
    int x = (i < n) ? g_hist[i] : 0;
    #pragma unroll
    for (int d = 16; d; d >>= 1) x += __shfl_down_sync(0xffffffffu, x, d);
    if (lane == 0) ws[w] = x;
    __syncthreads();
    if (w == 0) {
        int s = ws[lane];
        #pragma unroll
        for (int d = 16; d; d >>= 1) s += __shfl_down_sync(0xffffffffu, s, d);
        if (lane == 0) g_part[blockIdx.x] = s;
    }
}

// ---------------- 3b. exclusive scan of partials ----------------
__global__ void scan_part_kernel(int nb) {
    __shared__ int wsum[4];
    int t = threadIdx.x, lane = t & 31, w = t >> 5;
    int v = (t < nb) ? g_part[t] : 0;
    int x = v;
    #pragma unroll
    for (int d = 1; d < 32; d <<= 1) {
        int y = __shfl_up_sync(0xffffffffu, x, d);
        if (lane >= d) x += y;
    }
    if (lane == 31) wsum[w] = x;
    __syncthreads();
    if (t == 0) {
        int a = 0;
        #pragma unroll
        for (int k = 0; k < 4; k++) { int b = wsum[k]; wsum[k] = a; a += b; }
    }
    __syncthreads();
    if (t < nb) g_part[t] = x + wsum[w] - v;
    if (t == 0) g_off[0] = 0;
}

// ---------------- 3c. final block scans with base offset ----------------
__global__ __launch_bounds__(SBLK) void scan_final_kernel(int n) {
    __shared__ int ws[32];
    int tid = threadIdx.x, lane = tid & 31, w = tid >> 5;
    int i = blockIdx.x * SBLK + tid;
    int v = (i < n) ? g_hist[i] : 0;
    int x = v;
    #pragma unroll
    for (int d = 1; d < 32; d <<= 1) {
        int y = __shfl_up_sync(0xffffffffu, x, d);
        if (lane >= d) x += y;
    }
    if (lane == 31) ws[w] = x;
    __syncthreads();
    if (w == 0) {
        int s = ws[lane];
        #pragma unroll
        for (int d = 1; d < 32; d <<= 1) {
            int y = __shfl_up_sync(0xffffffffu, s, d);
            if (lane >= d) s += y;
        }
        ws[lane] = s;
    }
    __syncthreads();
    int incl = x + g_part[blockIdx.x] + (w > 0 ? ws[w - 1] : 0);
    if (i < n) {
        g_off[i + 1] = incl;
        g_cur[i]     = incl - v;
    }
}

// ---------------- 4. scatter edges (packed 8B records) ----------------
__global__ void scatter_kernel(const int* __restrict__ rows, const int* __restrict__ cols,
                               const float* __restrict__ vals, int e) {
    int i = blockIdx.x * blockDim.x + threadIdx.x;
    if (i < e) {
        int r = rows[i];
        ull rec = (ull)(uint)cols[i] | ((ull)__float_as_uint(vals[i]) << 32);
        int p = atomicAdd(&g_cur[r], 1);
        g_epack[p] = rec;
    }
}

// ---------------- 5. CSR SpMM over fp16 table: warp-per-node ----------------
// Each warp handles one node; lane t owns halves 8t..8t+7 (one uint4 per gather).
__global__ __launch_bounds__(128) void spmm_kernel(int n) {
    int node = blockIdx.x * 4 + (threadIdx.x >> 5);
    if (node >= n) return;
    int t = threadIdx.x & 31;
    const uint4* tab = (const uint4*)g_half;   // [N][32] uint4
    int beg = g_off[node], end = g_off[node + 1];
    float a0[8] = {0,0,0,0,0,0,0,0};
    float a1[8] = {0,0,0,0,0,0,0,0};
    float a2[8] = {0,0,0,0,0,0,0,0};
    float a3[8] = {0,0,0,0,0,0,0,0};
    int e = beg;
    for (; e + 4 <= end; e += 4) {
        ull r0 = g_epack[e],   r1 = g_epack[e+1];
        ull r2 = g_epack[e+2], r3 = g_epack[e+3];
        uint4 x0 = tab[(size_t)(uint)r0 * 32 + t];
        uint4 x1 = tab[(size_t)(uint)r1 * 32 + t];
        uint4 x2 = tab[(size_t)(uint)r2 * 32 + t];
        uint4 x3 = tab[(size_t)(uint)r3 * 32 + t];
        float v0 = __uint_as_float((uint)(r0 >> 32));
        float v1 = __uint_as_float((uint)(r1 >> 32));
        float v2 = __uint_as_float((uint)(r2 >> 32));
        float v3 = __uint_as_float((uint)(r3 >> 32));
        float2 p;
        p = __half22float2(u2h(x0.x)); a0[0] += v0*p.x; a0[1] += v0*p.y;
        p = __half22float2(u2h(x0.y)); a0[2] += v0*p.x; a0[3] += v0*p.y;
        p = __half22float2(u2h(x0.z)); a0[4] += v0*p.x; a0[5] += v0*p.y;
        p = __half22float2(u2h(x0.w)); a0[6] += v0*p.x; a0[7] += v0*p.y;
        p = __half22float2(u2h(x1.x)); a1[0] += v1*p.x; a1[1] += v1*p.y;
        p = __half22float2(u2h(x1.y)); a1[2] += v1*p.x; a1[3] += v1*p.y;
        p = __half22float2(u2h(x1.z)); a1[4] += v1*p.x; a1[5] += v1*p.y;
        p = __half22float2(u2h(x1.w)); a1[6] += v1*p.x; a1[7] += v1*p.y;
        p = __half22float2(u2h(x2.x)); a2[0] += v2*p.x; a2[1] += v2*p.y;
        p = __half22float2(u2h(x2.y)); a2[2] += v2*p.x; a2[3] += v2*p.y;
        p = __half22float2(u2h(x2.z)); a2[4] += v2*p.x; a2[5] += v2*p.y;
        p = __half22float2(u2h(x2.w)); a2[6] += v2*p.x; a2[7] += v2*p.y;
        p = __half22float2(u2h(x3.x)); a3[0] += v3*p.x; a3[1] += v3*p.y;
        p = __half22float2(u2h(x3.y)); a3[2] += v3*p.x; a3[3] += v3*p.y;
        p = __half22float2(u2h(x3.z)); a3[4] += v3*p.x; a3[5] += v3*p.y;
        p = __half22float2(u2h(x3.w)); a3[6] += v3*p.x; a3[7] += v3*p.y;
    }
    for (; e < end; e++) {
        ull r0 = g_epack[e];
        uint4 x = tab[(size_t)(uint)r0 * 32 + t];
        float v = __uint_as_float((uint)(r0 >> 32));
        float2 p;
        p = __half22float2(u2h(x.x)); a0[0] += v*p.x; a0[1] += v*p.y;
        p = __half22float2(u2h(x.y)); a0[2] += v*p.x; a0[3] += v*p.y;
        p = __half22float2(u2h(x.z)); a0[4] += v*p.x; a0[5] += v*p.y;
        p = __half22float2(u2h(x.w)); a0[6] += v*p.x; a0[7] += v*p.y;
    }
    float4 o0, o1;
    o0.x = (a0[0]+a1[0]) + (a2[0]+a3[0]);
    o0.y = (a0[1]+a1[1]) + (a2[1]+a3[1]);
    o0.z = (a0[2]+a1[2]) + (a2[2]+a3[2]);
    o0.w = (a0[3]+a1[3]) + (a2[3]+a3[3]);
    o1.x = (a0[4]+a1[4]) + (a2[4]+a3[4]);
    o1.y = (a0[5]+a1[5]) + (a2[5]+a3[5]);
    o1.z = (a0[6]+a1[6]) + (a2[6]+a3[6]);
    o1.w = (a0[7]+a1[7]) + (a2[7]+a3[7]);
    float4* dst = (float4*)(g_side + (size_t)node * D);
    dst[2*t]     = o0;
    dst[2*t + 1] = o1;
}

// ---------------- 6. fused dual GEMM via tf32 tensor cores ----------------
#define TBM 128
#define TBN 128
#define TBK 32
#define XSTR 36
#define TILE_F (TBM * XSTR)
#define GEMM_SMEM (4 * TILE_F * 4)        // 73728B

__global__ __launch_bounds__(256, 1) void gemm_mma_kernel(
    const float* __restrict__ ego,
    const float* __restrict__ W1, const float* __restrict__ b1,
    const float* __restrict__ W2, const float* __restrict__ b2,
    float* __restrict__ out, int n)
{
    extern __shared__ char smem_raw[];
    uint* Xs  = (uint*)smem_raw;
    uint* Xp  = Xs + TILE_F;
    uint* W1t = Xp + TILE_F;
    uint* W2t = W1t + TILE_F;

    const int tid  = threadIdx.x;
    const int lane = tid & 31;
    const int wid  = tid >> 5;
    const int wm   = (wid >> 2) * 64;
    const int wn   = (wid & 3) * 32;
    const int g    = lane >> 2;
    const int c    = lane & 3;

    const int node0 = blockIdx.x * TBM;
    const int jbase = blockIdx.y * TBN;

    const int pm   = tid >> 1;
    const int ph   = tid & 1;

    float acc1[4][4][4];
    float acc2[4][4][4];
    #pragma unroll
    for (int i = 0; i < 4; i++)
        #pragma unroll
        for (int j = 0; j < 4; j++)
            #pragma unroll
            for (int r = 0; r < 4; r++) { acc1[i][j][r] = 0.f; acc2[i][j][r] = 0.f; }

    int xrow = node0 + pm; if (xrow >= n) xrow = n - 1;
    const float4* egoR  = (const float4*)(ego    + (size_t)xrow * D);
    const float4* sideR = (const float4*)(g_side + (size_t)xrow * D);
    const float4* w1R   = (const float4*)(W1 + (size_t)(jbase + pm) * D);
    const float4* w2R   = (const float4*)(W2 + (size_t)(jbase + pm) * D);

    for (int ck = 0; ck < D / TBK; ck++) {
        const int kq0 = ck * (TBK / 4);
        __syncthreads();
        #pragma unroll
        for (int q = 0; q < 4; q++) {
            int f = ph * 4 + q;
            float4 e4 = egoR[kq0 + f];
            float4 s4 = sideR[kq0 + f];
            uint4 sv, pv;
            sv.x = f2tf32(e4.x + s4.x); sv.y = f2tf32(e4.y + s4.y);
            sv.z = f2tf32(e4.z + s4.z); sv.w = f2tf32(e4.w + s4.w);
            pv.x = f2tf32(e4.x * s4.x); pv.y = f2tf32(e4.y * s4.y);
            pv.z = f2tf32(e4.z * s4.z); pv.w = f2tf32(e4.w * s4.w);
            *(uint4*)(Xs + pm * XSTR + f * 4) = sv;
            *(uint4*)(Xp + pm * XSTR + f * 4) = pv;
        }
        #pragma unroll
        for (int q = 0; q < 4; q++) {
            int f = ph * 4 + q;
            float4 w1v = w1R[kq0 + f];
            float4 w2v = w2R[kq0 + f];
            uint4 a, b;
            a.x = f2tf32(w1v.x); a.y = f2tf32(w1v.y); a.z = f2tf32(w1v.z); a.w = f2tf32(w1v.w);
            b.x = f2tf32(w2v.x); b.y = f2tf32(w2v.y); b.z = f2tf32(w2v.z); b.w = f2tf32(w2v.w);
            *(uint4*)(W1t + pm * XSTR + f * 4) = a;
            *(uint4*)(W2t + pm * XSTR + f * 4) = b;
        }
        __syncthreads();
        #pragma unroll
        for (int s = 0; s < 4; s++) {
            uint aS[4][4], aP[4][4];
            #pragma unroll
            for (int am = 0; am < 4; am++) {
                int base = (wm + am * 16 + g) * XSTR + s * 8 + c;
                aS[am][0] = Xs[base];
                aS[am][1] = Xs[base + 8 * XSTR];
                aS[am][2] = Xs[base + 4];
                aS[am][3] = Xs[base + 8 * XSTR + 4];
                aP[am][0] = Xp[base];
                aP[am][1] = Xp[base + 8 * XSTR];
                aP[am][2] = Xp[base + 4];
                aP[am][3] = Xp[base + 8 * XSTR + 4];
            }
            uint bW1[4][2], bW2[4][2];
            #pragma unroll
            for (int bn = 0; bn < 4; bn++) {
                int base = (wn + bn * 8 + g) * XSTR + s * 8 + c;
                bW1[bn][0] = W1t[base];
                bW1[bn][1] = W1t[base + 4];
                bW2[bn][0] = W2t[base];
                bW2[bn][1] = W2t[base + 4];
            }
            #pragma unroll
            for (int am = 0; am < 4; am++)
                #pragma unroll
                for (int bn = 0; bn < 4; bn++) {
                    mma8(acc1[am][bn], aS[am], bW1[bn]);
                    mma8(acc2[am][bn], aP[am], bW2[bn]);
                }
        }
    }

    #pragma unroll
    for (int bn = 0; bn < 4; bn++) {
        int col = jbase + wn + bn * 8 + c * 2;
        float2 bb1 = *(const float2*)(b1 + col);
        float2 bb2 = *(const float2*)(b2 + col);
        #pragma unroll
        for (int am = 0; am < 4; am++) {
            int r0 = node0 + wm + am * 16 + g;
            int r1 = r0 + 8;
            if (r0 < n) {
                float2 o;
                o.x = lrelu(acc1[am][bn][0] + bb1.x) + lrelu(acc2[am][bn][0] + bb2.x);
                o.y = lrelu(acc1[am][bn][1] + bb1.y) + lrelu(acc2[am][bn][1] + bb2.y);
                *(float2*)(out + (size_t)r0 * D + col) = o;
            }
            if (r1 < n) {
                float2 o;
                o.x = lrelu(acc1[am][bn][2] + bb1.x) + lrelu(acc2[am][bn][2] + bb2.x);
                o.y = lrelu(acc1[am][bn][3] + bb1.y) + lrelu(acc2[am][bn][3] + bb2.y);
                *(float2*)(out + (size_t)r1 * D + col) = o;
            }
        }
    }
}

// ---------------- launch ----------------
extern "C" void kernel_launch(void* const* d_in, const int* in_sizes, int n_in,
                              void* d_out, int out_size) {
    const float* ego   = (const float*)d_in[0];
    const float* evals = (const float*)d_in[1];
    const float* W1    = (const float*)d_in[2];
    const float* b1    = (const float*)d_in[3];
    const float* W2    = (const float*)d_in[4];
    const float* b2    = (const float*)d_in[5];
    const int*   erows = (const int*)d_in[6];
    const int*   ecols = (const int*)d_in[7];
    float* out = (float*)d_out;

    int N = in_sizes[0] / D;
    int E = in_sizes[1];
    if (N > MAXN) N = MAXN;
    if (E > MAXE) E = MAXE;

    static bool attr_set = false;
    if (!attr_set) {
        cudaFuncSetAttribute(gemm_mma_kernel, cudaFuncAttributeMaxDynamicSharedMemorySize, GEMM_SMEM);
        attr_set = true;
    }

    int n4 = N * (D / 4);
    int zb = (N + 255) / 256;
    int cb = (n4 + 255) / 256;
    int nscan = (N + SBLK - 1) / SBLK;
    prep_kernel<<<zb + cb, 256>>>((const float4*)ego, n4, N, zb);
    hist_kernel<<<(E + 255) / 256, 256>>>(erows, E);
    scan_reduce_kernel<<<nscan, SBLK>>>(N);
    scan_part_kernel<<<1, 128>>>(nscan);
    scan_final_kernel<<<nscan, SBLK>>>(N);
    scatter_kernel<<<(E + 255) / 256, 256>>>(erows, ecols, evals, E);
    spmm_kernel<<<(N + 3) / 4, 128>>>(N);
    dim3 ggrid((N + TBM - 1) / TBM, D / TBN);
    gemm_mma_kernel<<<ggrid, 256, GEMM_SMEM>>>(ego, W1, b1, W2, b2, out, N);
}

// round 12
// speedup vs baseline: 1.4234x; 1.1139x over previous
#include <cuda_runtime.h>
#include <cuda_fp16.h>
#include <cstdint>

typedef unsigned long long ull;
typedef unsigned int uint;

#define MAXN 100000
#define MAXE 3200000
#define D 256
#define SBLK 1024
#define MAXPART 128

// ---------------- scratch ----------------
__device__ float  g_side[(size_t)MAXN * D];
__device__ __half g_half[(size_t)MAXN * D];
__device__ ull    g_epack[MAXE];
__device__ int    g_hist[MAXN];
__device__ int    g_off[MAXN + 1];
__device__ int    g_cur[MAXN];
__device__ int    g_part[MAXPART];
__device__ uint   g_w1t[D * D];     // W1 as tf32, row-major [j][k]
__device__ uint   g_w2t[D * D];     // W2 as tf32, row-major [j][k]

__device__ __forceinline__ float lrelu(float x) { return x > 0.0f ? x : 0.01f * x; }
__device__ __forceinline__ uint f2tf32(float f) {
    uint u; asm("cvt.rna.tf32.f32 %0, %1;" : "=r"(u) : "f"(f)); return u;
}
__device__ __forceinline__ uint h2u(__half2 h) { return *reinterpret_cast<uint*>(&h); }
__device__ __forceinline__ __half2 u2h(uint u) { return *reinterpret_cast<__half2*>(&u); }

// m16n8k8 tf32 mma, D += A*B  (fastest mma path reachable on plain sm_103 target)
__device__ __forceinline__ void mma8(float* d, const uint* a, const uint* b) {
    asm volatile(
        "mma.sync.aligned.m16n8k8.row.col.f32.tf32.tf32.f32 "
        "{%0,%1,%2,%3}, {%4,%5,%6,%7}, {%8,%9}, {%0,%1,%2,%3};"
        : "+f"(d[0]), "+f"(d[1]), "+f"(d[2]), "+f"(d[3])
        : "r"(a[0]), "r"(a[1]), "r"(a[2]), "r"(a[3]), "r"(b[0]), "r"(b[1]));
}
__device__ __forceinline__ void cpasync16(uint dst, const void* src) {
    asm volatile("cp.async.cg.shared.global [%0], [%1], 16;" :: "r"(dst), "l"(src) : "memory");
}
__device__ __forceinline__ uint smem_u32(const void* p) {
    uint a; asm("{ .reg .u64 t; cvta.to.shared.u64 t, %1; cvt.u32.u64 %0, t; }" : "=r"(a) : "l"(p));
    return a;
}

// ---------------- 0a. W -> tf32 pre-conversion ----------------
__global__ void wprep_kernel(const float* __restrict__ W1, const float* __restrict__ W2) {
    int i = blockIdx.x * 256 + threadIdx.x;
    g_w1t[i] = f2tf32(W1[i]);
    g_w2t[i] = f2tf32(W2[i]);
}

// ---------------- 0b. fused: zero hist + fp32->fp16 gather table ----------
__global__ void prep_kernel(const float4* __restrict__ ego4, int n4, int n, int zb) {
    if ((int)blockIdx.x < zb) {
        int i = blockIdx.x * 256 + threadIdx.x;
        if (i < n) g_hist[i] = 0;
    } else {
        int i = (blockIdx.x - zb) * 256 + threadIdx.x;
        if (i < n4) {
            float4 v = ego4[i];
            uint2 o;
            o.x = h2u(__floats2half2_rn(v.x, v.y));
            o.y = h2u(__floats2half2_rn(v.z, v.w));
            ((uint2*)g_half)[i] = o;
        }
    }
}

// ---------------- 2. histogram of edge rows ----------------
__global__ void hist_kernel(const int* __restrict__ rows, int e) {
    int i = blockIdx.x * blockDim.x + threadIdx.x;
    if (i < e) atomicAdd(&g_hist[rows[i]], 1);
}

// ---------------- 3a. per-block reduce of hist ----------------
__global__ __launch_bounds__(SBLK) void scan_reduce_kernel(int n) {
    __shared__ int ws[32];
    int tid = threadIdx.x, lane = tid & 31, w = tid >> 5;
    int i = blockIdx.x * SBLK + tid;
    int x = (i < n) ? g_hist[i] : 0;
    #pragma unroll
    for (int d = 16; d; d >>= 1) x += __shfl_down_sync(0xffffffffu, x, d);
    if (lane == 0) ws[w] = x;
    __syncthreads();
    if (w == 0) {
        int s = ws[lane];
        #pragma unroll
        for (int d = 16; d; d >>= 1) s += __shfl_down_sync(0xffffffffu, s, d);
        if (lane == 0) g_part[blockIdx.x] = s;
    }
}

// ---------------- 3b. exclusive scan of partials ----------------
__global__ void scan_part_kernel(int nb) {
    __shared__ int wsum[4];
    int t = threadIdx.x, lane = t & 31, w = t >> 5;
    int v = (t < nb) ? g_part[t] : 0;
    int x = v;
    #pragma unroll
    for (int d = 1; d < 32; d <<= 1) {
        int y = __shfl_up_sync(0xffffffffu, x, d);
        if (lane >= d) x += y;
    }
    if (lane == 31) wsum[w] = x;
    __syncthreads();
    if (t == 0) {
        int a = 0;
        #pragma unroll
        for (int k = 0; k < 4; k++) { int b = wsum[k]; wsum[k] = a; a += b; }
    }
    __syncthreads();
    if (t < nb) g_part[t] = x + wsum[w] - v;
    if (t == 0) g_off[0] = 0;
}

// ---------------- 3c. final block scans with base offset ----------------
__global__ __launch_bounds__(SBLK) void scan_final_kernel(int n) {
    __shared__ int ws[32];
    int tid = threadIdx.x, lane = tid & 31, w = tid >> 5;
    int i = blockIdx.x * SBLK + tid;
    int v = (i < n) ? g_hist[i] : 0;
    int x = v;
    #pragma unroll
    for (int d = 1; d < 32; d <<= 1) {
        int y = __shfl_up_sync(0xffffffffu, x, d);
        if (lane >= d) x += y;
    }
    if (lane == 31) ws[w] = x;
    __syncthreads();
    if (w == 0) {
        int s = ws[lane];
        #pragma unroll
        for (int d = 1; d < 32; d <<= 1) {
            int y = __shfl_up_sync(0xffffffffu, s, d);
            if (lane >= d) s += y;
        }
        ws[lane] = s;
    }
    __syncthreads();
    int incl = x + g_part[blockIdx.x] + (w > 0 ? ws[w - 1] : 0);
    if (i < n) {
        g_off[i + 1] = incl;
        g_cur[i]     = incl - v;
    }
}

// ---------------- 4. scatter edges (packed 8B records) ----------------
__global__ void scatter_kernel(const int* __restrict__ rows, const int* __restrict__ cols,
                               const float* __restrict__ vals, int e) {
    int i = blockIdx.x * blockDim.x + threadIdx.x;
    if (i < e) {
        int r = rows[i];
        ull rec = (ull)(uint)cols[i] | ((ull)__float_as_uint(vals[i]) << 32);
        int p = atomicAdd(&g_cur[r], 1);
        g_epack[p] = rec;
    }
}

// ---------------- 5. CSR SpMM over fp16 table: warp-per-node ----------------
__global__ __launch_bounds__(128) void spmm_kernel(int n) {
    int node = blockIdx.x * 4 + (threadIdx.x >> 5);
    if (node >= n) return;
    int t = threadIdx.x & 31;
    const uint4* tab = (const uint4*)g_half;
    int beg = g_off[node], end = g_off[node + 1];
    float a0[8] = {0,0,0,0,0,0,0,0};
    float a1[8] = {0,0,0,0,0,0,0,0};
    float a2[8] = {0,0,0,0,0,0,0,0};
    float a3[8] = {0,0,0,0,0,0,0,0};
    int e = beg;
    for (; e + 4 <= end; e += 4) {
        ull r0 = g_epack[e],   r1 = g_epack[e+1];
        ull r2 = g_epack[e+2], r3 = g_epack[e+3];
        uint4 x0 = tab[(size_t)(uint)r0 * 32 + t];
        uint4 x1 = tab[(size_t)(uint)r1 * 32 + t];
        uint4 x2 = tab[(size_t)(uint)r2 * 32 + t];
        uint4 x3 = tab[(size_t)(uint)r3 * 32 + t];
        float v0 = __uint_as_float((uint)(r0 >> 32));
        float v1 = __uint_as_float((uint)(r1 >> 32));
        float v2 = __uint_as_float((uint)(r2 >> 32));
        float v3 = __uint_as_float((uint)(r3 >> 32));
        float2 p;
        p = __half22float2(u2h(x0.x)); a0[0] += v0*p.x; a0[1] += v0*p.y;
        p = __half22float2(u2h(x0.y)); a0[2] += v0*p.x; a0[3] += v0*p.y;
        p = __half22float2(u2h(x0.z)); a0[4] += v0*p.x; a0[5] += v0*p.y;
        p = __half22float2(u2h(x0.w)); a0[6] += v0*p.x; a0[7] += v0*p.y;
        p = __half22float2(u2h(x1.x)); a1[0] += v1*p.x; a1[1] += v1*p.y;
        p = __half22float2(u2h(x1.y)); a1[2] += v1*p.x; a1[3] += v1*p.y;
        p = __half22float2(u2h(x1.z)); a1[4] += v1*p.x; a1[5] += v1*p.y;
        p = __half22float2(u2h(x1.w)); a1[6] += v1*p.x; a1[7] += v1*p.y;
        p = __half22float2(u2h(x2.x)); a2[0] += v2*p.x; a2[1] += v2*p.y;
        p = __half22float2(u2h(x2.y)); a2[2] += v2*p.x; a2[3] += v2*p.y;
        p = __half22float2(u2h(x2.z)); a2[4] += v2*p.x; a2[5] += v2*p.y;
        p = __half22float2(u2h(x2.w)); a2[6] += v2*p.x; a2[7] += v2*p.y;
        p = __half22float2(u2h(x3.x)); a3[0] += v3*p.x; a3[1] += v3*p.y;
        p = __half22float2(u2h(x3.y)); a3[2] += v3*p.x; a3[3] += v3*p.y;
        p = __half22float2(u2h(x3.z)); a3[4] += v3*p.x; a3[5] += v3*p.y;
        p = __half22float2(u2h(x3.w)); a3[6] += v3*p.x; a3[7] += v3*p.y;
    }
    for (; e < end; e++) {
        ull r0 = g_epack[e];
        uint4 x = tab[(size_t)(uint)r0 * 32 + t];
        float v = __uint_as_float((uint)(r0 >> 32));
        float2 p;
        p = __half22float2(u2h(x.x)); a0[0] += v*p.x; a0[1] += v*p.y;
        p = __half22float2(u2h(x.y)); a0[2] += v*p.x; a0[3] += v*p.y;
        p = __half22float2(u2h(x.z)); a0[4] += v*p.x; a0[5] += v*p.y;
        p = __half22float2(u2h(x.w)); a0[6] += v*p.x; a0[7] += v*p.y;
    }
    float4 o0, o1;
    o0.x = (a0[0]+a1[0]) + (a2[0]+a3[0]);
    o0.y = (a0[1]+a1[1]) + (a2[1]+a3[1]);
    o0.z = (a0[2]+a1[2]) + (a2[2]+a3[2]);
    o0.w = (a0[3]+a1[3]) + (a2[3]+a3[3]);
    o1.x = (a0[4]+a1[4]) + (a2[4]+a3[4]);
    o1.y = (a0[5]+a1[5]) + (a2[5]+a3[5]);
    o1.z = (a0[6]+a1[6]) + (a2[6]+a3[6]);
    o1.w = (a0[7]+a1[7]) + (a2[7]+a3[7]);
    float4* dst = (float4*)(g_side + (size_t)node * D);
    dst[2*t]     = o0;
    dst[2*t + 1] = o1;
}

// ---------------- 6. fused dual GEMM, tf32 mma, 2-stage pipeline ----------
// Block tile 128x128, BK=32, 8 warps. Double-buffered smem; W tiles arrive
// via cp.async from pre-converted tf32 globals; X tiles LDG-prefetched into
// registers and cvt+STS'd after the mma block. One __syncthreads per chunk.
#define TBM 128
#define TBN 128
#define TBK 32
#define XSTR 36
#define TILE_F (TBM * XSTR)            // 4608 uints per tile
#define STAGE_F (4 * TILE_F)           // 18432 uints per stage
#define GEMM_SMEM (2 * STAGE_F * 4)    // 147456 B

__global__ __launch_bounds__(256, 1) void gemm_mma_kernel(
    const float* __restrict__ ego,
    const float* __restrict__ b1, const float* __restrict__ b2,
    float* __restrict__ out, int n)
{
    extern __shared__ char smem_raw[];
    uint* sm = (uint*)smem_raw;
    const uint smb = smem_u32(smem_raw);

    const int tid  = threadIdx.x;
    const int lane = tid & 31;
    const int wid  = tid >> 5;
    const int wm   = (wid >> 2) * 64;
    const int wn   = (wid & 3) * 32;
    const int g    = lane >> 2;
    const int c    = lane & 3;

    const int node0 = blockIdx.x * TBM;
    const int jbase = blockIdx.y * TBN;

    const int pm   = tid >> 1;      // row 0..127
    const int ph   = tid & 1;       // k-half

    float acc1[4][4][4];
    float acc2[4][4][4];
    #pragma unroll
    for (int i = 0; i < 4; i++)
        #pragma unroll
        for (int j = 0; j < 4; j++)
            #pragma unroll
            for (int r = 0; r < 4; r++) { acc1[i][j][r] = 0.f; acc2[i][j][r] = 0.f; }

    int xrow = node0 + pm; if (xrow >= n) xrow = n - 1;
    const float4* egoR  = (const float4*)(ego    + (size_t)xrow * D);
    const float4* sideR = (const float4*)(g_side + (size_t)xrow * D);
    // W cp.async: this thread copies 4x16B per matrix: row jbase+pm, k-half ph
    const uint* w1src = g_w1t + (size_t)(jbase + pm) * D + ph * 16;
    const uint* w2src = g_w2t + (size_t)(jbase + pm) * D + ph * 16;
    // smem offsets (uints) within a stage
    const uint xoff = pm * XSTR + ph * 16;     // X sts/W dst base (thread's 16 floats)

    // helper lambdas via macros
    #define W_CPASYNC(stage, ck_) do {                                            \
        uint dbase = smb + (((stage) * STAGE_F) + 2 * TILE_F + xoff) * 4;          \
        const uint* s1 = w1src + (ck_) * TBK;                                     \
        const uint* s2 = w2src + (ck_) * TBK;                                     \
        _Pragma("unroll")                                                          \
        for (int i = 0; i < 4; i++) {                                              \
            cpasync16(dbase + i * 16, s1 + i * 4);                                 \
            cpasync16(dbase + TILE_F * 4 + i * 16, s2 + i * 4);                    \
        }                                                                          \
        asm volatile("cp.async.commit_group;" ::: "memory");                       \
    } while (0)

    #define X_LDG(ck_, e4_, s4_) do {                                             \
        int q0 = (ck_) * 8 + ph * 4;                                               \
        _Pragma("unroll")                                                          \
        for (int q = 0; q < 4; q++) { e4_[q] = egoR[q0 + q]; s4_[q] = sideR[q0 + q]; } \
    } while (0)

    #define X_STS(stage, e4_, s4_) do {                                           \
        uint* Xs = sm + (stage) * STAGE_F;                                         \
        uint* Xp = Xs + TILE_F;                                                    \
        _Pragma("unroll")                                                          \
        for (int q = 0; q < 4; q++) {                                              \
            uint4 sv, pv;                                                          \
            sv.x = f2tf32(e4_[q].x + s4_[q].x); sv.y = f2tf32(e4_[q].y + s4_[q].y);\
            sv.z = f2tf32(e4_[q].z + s4_[q].z); sv.w = f2tf32(e4_[q].w + s4_[q].w);\
            pv.x = f2tf32(e4_[q].x * s4_[q].x); pv.y = f2tf32(e4_[q].y * s4_[q].y);\
            pv.z = f2tf32(e4_[q].z * s4_[q].z); pv.w = f2tf32(e4_[q].w * s4_[q].w);\
            *(uint4*)(Xs + xoff + q * 4) = sv;                                     \
            *(uint4*)(Xp + xoff + q * 4) = pv;                                     \
        }                                                                          \
    } while (0)

    // ---- prologue: stage 0 for ck=0 ----
    {
        float4 e4[4], s4[4];
        W_CPASYNC(0, 0);
        X_LDG(0, e4, s4);
        X_STS(0, e4, s4);
        asm volatile("cp.async.wait_group 0;" ::: "memory");
        __syncthreads();
    }

    for (int ck = 0; ck < D / TBK; ck++) {
        const int st = ck & 1;
        float4 e4[4], s4[4];
        if (ck < 7) {
            X_LDG(ck + 1, e4, s4);       // issue early; consumed after mma
            W_CPASYNC(st ^ 1, ck + 1);   // safe: all warps past sync of prev iter
        }
        // ---- compute on stage st ----
        {
            uint* Xs  = sm + st * STAGE_F;
            uint* Xp  = Xs + TILE_F;
            uint* W1t = Xp + TILE_F;
            uint* W2t = W1t + TILE_F;
            #pragma unroll
            for (int s = 0; s < 4; s++) {
                uint aS[4][4], aP[4][4];
                #pragma unroll
                for (int am = 0; am < 4; am++) {
                    int base = (wm + am * 16 + g) * XSTR + s * 8 + c;
                    aS[am][0] = Xs[base];
                    aS[am][1] = Xs[base + 8 * XSTR];
                    aS[am][2] = Xs[base + 4];
                    aS[am][3] = Xs[base + 8 * XSTR + 4];
                    aP[am][0] = Xp[base];
                    aP[am][1] = Xp[base + 8 * XSTR];
                    aP[am][2] = Xp[base + 4];
                    aP[am][3] = Xp[base + 8 * XSTR + 4];
                }
                uint bW1[4][2], bW2[4][2];
                #pragma unroll
                for (int bn = 0; bn < 4; bn++) {
                    int base = (wn + bn * 8 + g) * XSTR + s * 8 + c;
                    bW1[bn][0] = W1t[base];
                    bW1[bn][1] = W1t[base + 4];
                    bW2[bn][0] = W2t[base];
                    bW2[bn][1] = W2t[base + 4];
                }
                #pragma unroll
                for (int am = 0; am < 4; am++)
                    #pragma unroll
                    for (int bn = 0; bn < 4; bn++) {
                        mma8(acc1[am][bn], aS[am], bW1[bn]);
                        mma8(acc2[am][bn], aP[am], bW2[bn]);
                    }
            }
        }
        if (ck < 7) {
            X_STS(st ^ 1, e4, s4);
            asm volatile("cp.async.wait_group 0;" ::: "memory");
        }
        __syncthreads();
    }

    // ---- epilogue: bias + leaky_relu + add ----
    #pragma unroll
    for (int bn = 0; bn < 4; bn++) {
        int col = jbase + wn + bn * 8 + c * 2;
        float2 bb1 = *(const float2*)(b1 + col);
        float2 bb2 = *(const float2*)(b2 + col);
        #pragma unroll
        for (int am = 0; am < 4; am++) {
            int r0 = node0 + wm + am * 16 + g;
            int r1 = r0 + 8;
            if (r0 < n) {
                float2 o;
                o.x = lrelu(acc1[am][bn][0] + bb1.x) + lrelu(acc2[am][bn][0] + bb2.x);
                o.y = lrelu(acc1[am][bn][1] + bb1.y) + lrelu(acc2[am][bn][1] + bb2.y);
                *(float2*)(out + (size_t)r0 * D + col) = o;
            }
            if (r1 < n) {
                float2 o;
                o.x = lrelu(acc1[am][bn][2] + bb1.x) + lrelu(acc2[am][bn][2] + bb2.x);
                o.y = lrelu(acc1[am][bn][3] + bb1.y) + lrelu(acc2[am][bn][3] + bb2.y);
                *(float2*)(out + (size_t)r1 * D + col) = o;
            }
        }
    }
}

// ---------------- launch ----------------
extern "C" void kernel_launch(void* const* d_in, const int* in_sizes, int n_in,
                              void* d_out, int out_size) {
    const float* ego   = (const float*)d_in[0];
    const float* evals = (const float*)d_in[1];
    const float* W1    = (const float*)d_in[2];
    const float* b1    = (const float*)d_in[3];
    const float* W2    = (const float*)d_in[4];
    const float* b2    = (const float*)d_in[5];
    const int*   erows = (const int*)d_in[6];
    const int*   ecols = (const int*)d_in[7];
    float* out = (float*)d_out;

    int N = in_sizes[0] / D;
    int E = in_sizes[1];
    if (N > MAXN) N = MAXN;
    if (E > MAXE) E = MAXE;

    static bool attr_set = false;
    if (!attr_set) {
        cudaFuncSetAttribute(gemm_mma_kernel, cudaFuncAttributeMaxDynamicSharedMemorySize, GEMM_SMEM);
        attr_set = true;
    }

    int n4 = N * (D / 4);
    int zb = (N + 255) / 256;
    int cb = (n4 + 255) / 256;
    int nscan = (N + SBLK - 1) / SBLK;
    wprep_kernel<<<D * D / 256, 256>>>(W1, W2);
    prep_kernel<<<zb + cb, 256>>>((const float4*)ego, n4, N, zb);
    hist_kernel<<<(E + 255) / 256, 256>>>(erows, E);
    scan_reduce_kernel<<<nscan, SBLK>>>(N);
    scan_part_kernel<<<1, 128>>>(nscan);
    scan_final_kernel<<<nscan, SBLK>>>(N);
    scatter_kernel<<<(E + 255) / 256, 256>>>(erows, ecols, evals, E);
    spmm_kernel<<<(N + 3) / 4, 128>>>(N);
    dim3 ggrid((N + TBM - 1) / TBM, D / TBN);
    gemm_mma_kernel<<<ggrid, 256, GEMM_SMEM>>>(ego, b1, b2, out, N);
}

// round 13
// speedup vs baseline: 1.4300x; 1.0046x over previous
#include <cuda_runtime.h>
#include <cuda_fp16.h>
#include <cstdint>

typedef unsigned long long ull;
typedef unsigned int uint;

#define MAXN 100000
#define MAXE 3200000
#define D 256
#define SBLK 1024
#define MAXPART 128

// ---------------- scratch ----------------
__device__ float  g_side[(size_t)MAXN * D];
__device__ __half g_half[(size_t)MAXN * D];
__device__ ull    g_epack[MAXE];
__device__ int    g_hist[MAXN];
__device__ int    g_off[MAXN + 1];
__device__ int    g_cur[MAXN];
__device__ int    g_part[MAXPART];
__device__ uint   g_w1t[D * D];     // W1 as tf32, row-major [j][k]
__device__ uint   g_w2t[D * D];     // W2 as tf32, row-major [j][k]

__device__ __forceinline__ float lrelu(float x) { return x > 0.0f ? x : 0.01f * x; }
__device__ __forceinline__ uint f2tf32(float f) {
    uint u; asm("cvt.rna.tf32.f32 %0, %1;" : "=r"(u) : "f"(f)); return u;
}
__device__ __forceinline__ uint h2u(__half2 h) { return *reinterpret_cast<uint*>(&h); }
__device__ __forceinline__ __half2 u2h(uint u) { return *reinterpret_cast<__half2*>(&u); }

// m16n8k8 tf32 mma, D += A*B  (fastest mma path reachable on plain sm_103 target)
__device__ __forceinline__ void mma8(float* d, const uint* a, const uint* b) {
    asm volatile(
        "mma.sync.aligned.m16n8k8.row.col.f32.tf32.tf32.f32 "
        "{%0,%1,%2,%3}, {%4,%5,%6,%7}, {%8,%9}, {%0,%1,%2,%3};"
        : "+f"(d[0]), "+f"(d[1]), "+f"(d[2]), "+f"(d[3])
        : "r"(a[0]), "r"(a[1]), "r"(a[2]), "r"(a[3]), "r"(b[0]), "r"(b[1]));
}
__device__ __forceinline__ void cpasync16(uint dst, const void* src) {
    asm volatile("cp.async.cg.shared.global [%0], [%1], 16;" :: "r"(dst), "l"(src) : "memory");
}
__device__ __forceinline__ uint smem_u32(const void* p) {
    uint a; asm("{ .reg .u64 t; cvta.to.shared.u64 t, %1; cvt.u32.u64 %0, t; }" : "=r"(a) : "l"(p));
    return a;
}

// ---------------- 0a. W -> tf32 pre-conversion ----------------
__global__ void wprep_kernel(const float* __restrict__ W1, const float* __restrict__ W2) {
    int i = blockIdx.x * 256 + threadIdx.x;
    g_w1t[i] = f2tf32(W1[i]);
    g_w2t[i] = f2tf32(W2[i]);
}

// ---------------- 0b. fused: zero hist + fp32->fp16 gather table ----------
__global__ void prep_kernel(const float4* __restrict__ ego4, int n4, int n, int zb) {
    if ((int)blockIdx.x < zb) {
        int i = blockIdx.x * 256 + threadIdx.x;
        if (i < n) g_hist[i] = 0;
    } else {
        int i = (blockIdx.x - zb) * 256 + threadIdx.x;
        if (i < n4) {
            float4 v = ego4[i];
            uint2 o;
            o.x = h2u(__floats2half2_rn(v.x, v.y));
            o.y = h2u(__floats2half2_rn(v.z, v.w));
            ((uint2*)g_half)[i] = o;
        }
    }
}

// ---------------- 2. histogram of edge rows ----------------
__global__ void hist_kernel(const int* __restrict__ rows, int e) {
    int i = blockIdx.x * blockDim.x + threadIdx.x;
    if (i < e) atomicAdd(&g_hist[rows[i]], 1);
}

// ---------------- 3a. per-block reduce of hist ----------------
__global__ __launch_bounds__(SBLK) void scan_reduce_kernel(int n) {
    __shared__ int ws[32];
    int tid = threadIdx.x, lane = tid & 31, w = tid >> 5;
    int i = blockIdx.x * SBLK + tid;
    int x = (i < n) ? g_hist[i] : 0;
    #pragma unroll
    for (int d = 16; d; d >>= 1) x += __shfl_down_sync(0xffffffffu, x, d);
    if (lane == 0) ws[w] = x;
    __syncthreads();
    if (w == 0) {
        int s = ws[lane];
        #pragma unroll
        for (int d = 16; d; d >>= 1) s += __shfl_down_sync(0xffffffffu, s, d);
        if (lane == 0) g_part[blockIdx.x] = s;
    }
}

// ---------------- 3b. exclusive scan of partials ----------------
__global__ void scan_part_kernel(int nb) {
    __shared__ int wsum[4];
    int t = threadIdx.x, lane = t & 31, w = t >> 5;
    int v = (t < nb) ? g_part[t] : 0;
    int x = v;
    #pragma unroll
    for (int d = 1; d < 32; d <<= 1) {
        int y = __shfl_up_sync(0xffffffffu, x, d);
        if (lane >= d) x += y;
    }
    if (lane == 31) wsum[w] = x;
    __syncthreads();
    if (t == 0) {
        int a = 0;
        #pragma unroll
        for (int k = 0; k < 4; k++) { int b = wsum[k]; wsum[k] = a; a += b; }
    }
    __syncthreads();
    if (t < nb) g_part[t] = x + wsum[w] - v;
    if (t == 0) g_off[0] = 0;
}

// ---------------- 3c. final block scans with base offset ----------------
__global__ __launch_bounds__(SBLK) void scan_final_kernel(int n) {
    __shared__ int ws[32];
    int tid = threadIdx.x, lane = tid & 31, w = tid >> 5;
    int i = blockIdx.x * SBLK + tid;
    int v = (i < n) ? g_hist[i] : 0;
    int x = v;
    #pragma unroll
    for (int d = 1; d < 32; d <<= 1) {
        int y = __shfl_up_sync(0xffffffffu, x, d);
        if (lane >= d) x += y;
    }
    if (lane == 31) ws[w] = x;
    __syncthreads();
    if (w == 0) {
        int s = ws[lane];
        #pragma unroll
        for (int d = 1; d < 32; d <<= 1) {
            int y = __shfl_up_sync(0xffffffffu, s, d);
            if (lane >= d) s += y;
        }
        ws[lane] = s;
    }
    __syncthreads();
    int incl = x + g_part[blockIdx.x] + (w > 0 ? ws[w - 1] : 0);
    if (i < n) {
        g_off[i + 1] = incl;
        g_cur[i]     = incl - v;
    }
}

// ---------------- 4. scatter edges (packed 8B records) ----------------
__global__ void scatter_kernel(const int* __restrict__ rows, const int* __restrict__ cols,
                               const float* __restrict__ vals, int e) {
    int i = blockIdx.x * blockDim.x + threadIdx.x;
    if (i < e) {
        int r = rows[i];
        ull rec = (ull)(uint)cols[i] | ((ull)__float_as_uint(vals[i]) << 32);
        int p = atomicAdd(&g_cur[r], 1);
        g_epack[p] = rec;
    }
}

// ---------------- 5. CSR SpMM: warp-per-node, warp-staged edge records ------
// Records for a 32-edge window are loaded cooperatively (one per lane, single
// coalesced 256B load) and distributed via shfl, so gather LDGs never wait on
// a serial record fetch.
__global__ __launch_bounds__(128) void spmm_kernel(int n) {
    int node = blockIdx.x * 4 + (threadIdx.x >> 5);
    if (node >= n) return;
    int lane = threadIdx.x & 31;
    const uint4* tab = (const uint4*)g_half;
    int beg = g_off[node], end = g_off[node + 1];
    float a0[8] = {0,0,0,0,0,0,0,0};
    float a1[8] = {0,0,0,0,0,0,0,0};
    float a2[8] = {0,0,0,0,0,0,0,0};
    float a3[8] = {0,0,0,0,0,0,0,0};

    for (int base = beg; base < end; base += 32) {
        int cnt = end - base; if (cnt > 32) cnt = 32;
        uint lo = 0, hi = 0;
        if (lane < cnt) {
            ull rec = g_epack[base + lane];
            lo = (uint)rec; hi = (uint)(rec >> 32);
        }
        int j = 0;
        for (; j + 4 <= cnt; j += 4) {
            uint  c0 = __shfl_sync(0xffffffffu, lo, j);
            uint  c1 = __shfl_sync(0xffffffffu, lo, j + 1);
            uint  c2 = __shfl_sync(0xffffffffu, lo, j + 2);
            uint  c3 = __shfl_sync(0xffffffffu, lo, j + 3);
            float v0 = __uint_as_float(__shfl_sync(0xffffffffu, hi, j));
            float v1 = __uint_as_float(__shfl_sync(0xffffffffu, hi, j + 1));
            float v2 = __uint_as_float(__shfl_sync(0xffffffffu, hi, j + 2));
            float v3 = __uint_as_float(__shfl_sync(0xffffffffu, hi, j + 3));
            uint4 x0 = tab[(size_t)c0 * 32 + lane];
            uint4 x1 = tab[(size_t)c1 * 32 + lane];
            uint4 x2 = tab[(size_t)c2 * 32 + lane];
            uint4 x3 = tab[(size_t)c3 * 32 + lane];
            float2 p;
            p = __half22float2(u2h(x0.x)); a0[0] += v0*p.x; a0[1] += v0*p.y;
            p = __half22float2(u2h(x0.y)); a0[2] += v0*p.x; a0[3] += v0*p.y;
            p = __half22float2(u2h(x0.z)); a0[4] += v0*p.x; a0[5] += v0*p.y;
            p = __half22float2(u2h(x0.w)); a0[6] += v0*p.x; a0[7] += v0*p.y;
            p = __half22float2(u2h(x1.x)); a1[0] += v1*p.x; a1[1] += v1*p.y;
            p = __half22float2(u2h(x1.y)); a1[2] += v1*p.x; a1[3] += v1*p.y;
            p = __half22float2(u2h(x1.z)); a1[4] += v1*p.x; a1[5] += v1*p.y;
            p = __half22float2(u2h(x1.w)); a1[6] += v1*p.x; a1[7] += v1*p.y;
            p = __half22float2(u2h(x2.x)); a2[0] += v2*p.x; a2[1] += v2*p.y;
            p = __half22float2(u2h(x2.y)); a2[2] += v2*p.x; a2[3] += v2*p.y;
            p = __half22float2(u2h(x2.z)); a2[4] += v2*p.x; a2[5] += v2*p.y;
            p = __half22float2(u2h(x2.w)); a2[6] += v2*p.x; a2[7] += v2*p.y;
            p = __half22float2(u2h(x3.x)); a3[0] += v3*p.x; a3[1] += v3*p.y;
            p = __half22float2(u2h(x3.y)); a3[2] += v3*p.x; a3[3] += v3*p.y;
            p = __half22float2(u2h(x3.z)); a3[4] += v3*p.x; a3[5] += v3*p.y;
            p = __half22float2(u2h(x3.w)); a3[6] += v3*p.x; a3[7] += v3*p.y;
        }
        for (; j < cnt; j++) {
            uint  c = __shfl_sync(0xffffffffu, lo, j);
            float v = __uint_as_float(__shfl_sync(0xffffffffu, hi, j));
            uint4 x = tab[(size_t)c * 32 + lane];
            float2 p;
            p = __half22float2(u2h(x.x)); a0[0] += v*p.x; a0[1] += v*p.y;
            p = __half22float2(u2h(x.y)); a0[2] += v*p.x; a0[3] += v*p.y;
            p = __half22float2(u2h(x.z)); a0[4] += v*p.x; a0[5] += v*p.y;
            p = __half22float2(u2h(x.w)); a0[6] += v*p.x; a0[7] += v*p.y;
        }
    }
    float4 o0, o1;
    o0.x = (a0[0]+a1[0]) + (a2[0]+a3[0]);
    o0.y = (a0[1]+a1[1]) + (a2[1]+a3[1]);
    o0.z = (a0[2]+a1[2]) + (a2[2]+a3[2]);
    o0.w = (a0[3]+a1[3]) + (a2[3]+a3[3]);
    o1.x = (a0[4]+a1[4]) + (a2[4]+a3[4]);
    o1.y = (a0[5]+a1[5]) + (a2[5]+a3[5]);
    o1.z = (a0[6]+a1[6]) + (a2[6]+a3[6]);
    o1.w = (a0[7]+a1[7]) + (a2[7]+a3[7]);
    float4* dst = (float4*)(g_side + (size_t)node * D);
    dst[2*lane]     = o0;
    dst[2*lane + 1] = o1;
}

// ---------------- 6. fused dual GEMM, tf32 mma, 2-stage pipeline ----------
#define TBM 128
#define TBN 128
#define TBK 32
#define XSTR 36
#define TILE_F (TBM * XSTR)            // 4608 uints per tile
#define STAGE_F (4 * TILE_F)           // 18432 uints per stage
#define GEMM_SMEM (2 * STAGE_F * 4)    // 147456 B

__global__ __launch_bounds__(256, 1) void gemm_mma_kernel(
    const float* __restrict__ ego,
    const float* __restrict__ b1, const float* __restrict__ b2,
    float* __restrict__ out, int n)
{
    extern __shared__ char smem_raw[];
    uint* sm = (uint*)smem_raw;
    const uint smb = smem_u32(smem_raw);

    const int tid  = threadIdx.x;
    const int lane = tid & 31;
    const int wid  = tid >> 5;
    const int wm   = (wid >> 2) * 64;
    const int wn   = (wid & 3) * 32;
    const int g    = lane >> 2;
    const int c    = lane & 3;

    const int node0 = blockIdx.x * TBM;
    const int jbase = blockIdx.y * TBN;

    const int pm   = tid >> 1;
    const int ph   = tid & 1;

    float acc1[4][4][4];
    float acc2[4][4][4];
    #pragma unroll
    for (int i = 0; i < 4; i++)
        #pragma unroll
        for (int j = 0; j < 4; j++)
            #pragma unroll
            for (int r = 0; r < 4; r++) { acc1[i][j][r] = 0.f; acc2[i][j][r] = 0.f; }

    int xrow = node0 + pm; if (xrow >= n) xrow = n - 1;
    const float4* egoR  = (const float4*)(ego    + (size_t)xrow * D);
    const float4* sideR = (const float4*)(g_side + (size_t)xrow * D);
    const uint* w1src = g_w1t + (size_t)(jbase + pm) * D + ph * 16;
    const uint* w2src = g_w2t + (size_t)(jbase + pm) * D + ph * 16;
    const uint xoff = pm * XSTR + ph * 16;

    #define W_CPASYNC(stage, ck_) do {                                            \
        uint dbase = smb + (((stage) * STAGE_F) + 2 * TILE_F + xoff) * 4;          \
        const uint* s1 = w1src + (ck_) * TBK;                                     \
        const uint* s2 = w2src + (ck_) * TBK;                                     \
        _Pragma("unroll")                                                          \
        for (int i = 0; i < 4; i++) {                                              \
            cpasync16(dbase + i * 16, s1 + i * 4);                                 \
            cpasync16(dbase + TILE_F * 4 + i * 16, s2 + i * 4);                    \
        }                                                                          \
        asm volatile("cp.async.commit_group;" ::: "memory");                       \
    } while (0)

    #define X_LDG(ck_, e4_, s4_) do {                                             \
        int q0 = (ck_) * 8 + ph * 4;                                               \
        _Pragma("unroll")                                                          \
        for (int q = 0; q < 4; q++) { e4_[q] = egoR[q0 + q]; s4_[q] = sideR[q0 + q]; } \
    } while (0)

    #define X_STS(stage, e4_, s4_) do {                                           \
        uint* Xs = sm + (stage) * STAGE_F;                                         \
        uint* Xp = Xs + TILE_F;                                                    \
        _Pragma("unroll")                                                          \
        for (int q = 0; q < 4; q++) {                                              \
            uint4 sv, pv;                                                          \
            sv.x = f2tf32(e4_[q].x + s4_[q].x); sv.y = f2tf32(e4_[q].y + s4_[q].y);\
            sv.z = f2tf32(e4_[q].z + s4_[q].z); sv.w = f2tf32(e4_[q].w + s4_[q].w);\
            pv.x = f2tf32(e4_[q].x * s4_[q].x); pv.y = f2tf32(e4_[q].y * s4_[q].y);\
            pv.z = f2tf32(e4_[q].z * s4_[q].z); pv.w = f2tf32(e4_[q].w * s4_[q].w);\
            *(uint4*)(Xs + xoff + q * 4) = sv;                                     \
            *(uint4*)(Xp + xoff + q * 4) = pv;                                     \
        }                                                                          \
    } while (0)

    {
        float4 e4[4], s4[4];
        W_CPASYNC(0, 0);
        X_LDG(0, e4, s4);
        X_STS(0, e4, s4);
        asm volatile("cp.async.wait_group 0;" ::: "memory");
        __syncthreads();
    }

    for (int ck = 0; ck < D / TBK; ck++) {
        const int st = ck & 1;
        float4 e4[4], s4[4];
        if (ck < 7) {
            X_LDG(ck + 1, e4, s4);
            W_CPASYNC(st ^ 1, ck + 1);
        }
        {
            uint* Xs  = sm + st * STAGE_F;
            uint* Xp  = Xs + TILE_F;
            uint* W1t = Xp + TILE_F;
            uint* W2t = W1t + TILE_F;
            #pragma unroll
            for (int s = 0; s < 4; s++) {
                uint aS[4][4], aP[4][4];
                #pragma unroll
                for (int am = 0; am < 4; am++) {
                    int base = (wm + am * 16 + g) * XSTR + s * 8 + c;
                    aS[am][0] = Xs[base];
                    aS[am][1] = Xs[base + 8 * XSTR];
                    aS[am][2] = Xs[base + 4];
                    aS[am][3] = Xs[base + 8 * XSTR + 4];
                    aP[am][0] = Xp[base];
                    aP[am][1] = Xp[base + 8 * XSTR];
                    aP[am][2] = Xp[base + 4];
                    aP[am][3] = Xp[base + 8 * XSTR + 4];
                }
                uint bW1[4][2], bW2[4][2];
                #pragma unroll
                for (int bn = 0; bn < 4; bn++) {
                    int base = (wn + bn * 8 + g) * XSTR + s * 8 + c;
                    bW1[bn][0] = W1t[base];
                    bW1[bn][1] = W1t[base + 4];
                    bW2[bn][0] = W2t[base];
                    bW2[bn][1] = W2t[base + 4];
                }
                #pragma unroll
                for (int am = 0; am < 4; am++)
                    #pragma unroll
                    for (int bn = 0; bn < 4; bn++) {
                        mma8(acc1[am][bn], aS[am], bW1[bn]);
                        mma8(acc2[am][bn], aP[am], bW2[bn]);
                    }
            }
        }
        if (ck < 7) {
            X_STS(st ^ 1, e4, s4);
            asm volatile("cp.async.wait_group 0;" ::: "memory");
        }
        __syncthreads();
    }

    #pragma unroll
    for (int bn = 0; bn < 4; bn++) {
        int col = jbase + wn + bn * 8 + c * 2;
        float2 bb1 = *(const float2*)(b1 + col);
        float2 bb2 = *(const float2*)(b2 + col);
        #pragma unroll
        for (int am = 0; am < 4; am++) {
            int r0 = node0 + wm + am * 16 + g;
            int r1 = r0 + 8;
            if (r0 < n) {
                float2 o;
                o.x = lrelu(acc1[am][bn][0] + bb1.x) + lrelu(acc2[am][bn][0] + bb2.x);
                o.y = lrelu(acc1[am][bn][1] + bb1.y) + lrelu(acc2[am][bn][1] + bb2.y);
                *(float2*)(out + (size_t)r0 * D + col) = o;
            }
            if (r1 < n) {
                float2 o;
                o.x = lrelu(acc1[am][bn][2] + bb1.x) + lrelu(acc2[am][bn][2] + bb2.x);
                o.y = lrelu(acc1[am][bn][3] + bb1.y) + lrelu(acc2[am][bn][3] + bb2.y);
                *(float2*)(out + (size_t)r1 * D + col) = o;
            }
        }
    }
}

// ---------------- launch ----------------
extern "C" void kernel_launch(void* const* d_in, const int* in_sizes, int n_in,
                              void* d_out, int out_size) {
    const float* ego   = (const float*)d_in[0];
    const float* evals = (const float*)d_in[1];
    const float* W1    = (const float*)d_in[2];
    const float* b1    = (const float*)d_in[3];
    const float* W2    = (const float*)d_in[4];
    const float* b2    = (const float*)d_in[5];
    const int*   erows = (const int*)d_in[6];
    const int*   ecols = (const int*)d_in[7];
    float* out = (float*)d_out;

    int N = in_sizes[0] / D;
    int E = in_sizes[1];
    if (N > MAXN) N = MAXN;
    if (E > MAXE) E = MAXE;

    static bool attr_set = false;
    if (!attr_set) {
        cudaFuncSetAttribute(gemm_mma_kernel, cudaFuncAttributeMaxDynamicSharedMemorySize, GEMM_SMEM);
        attr_set = true;
    }

    int n4 = N * (D / 4);
    int zb = (N + 255) / 256;
    int cb = (n4 + 255) / 256;
    int nscan = (N + SBLK - 1) / SBLK;
    wprep_kernel<<<D * D / 256, 256>>>(W1, W2);
    prep_kernel<<<zb + cb, 256>>>((const float4*)ego, n4, N, zb);
    hist_kernel<<<(E + 255) / 256, 256>>>(erows, E);
    scan_reduce_kernel<<<nscan, SBLK>>>(N);
    scan_part_kernel<<<1, 128>>>(nscan);
    scan_final_kernel<<<nscan, SBLK>>>(N);
    scatter_kernel<<<(E + 255) / 256, 256>>>(erows, ecols, evals, E);
    spmm_kernel<<<(N + 3) / 4, 128>>>(N);
    dim3 ggrid((N + TBM - 1) / TBM, D / TBN);
    gemm_mma_kernel<<<ggrid, 256, GEMM_SMEM>>>(ego, b1, b2, out, N);
}